// round 2
// baseline (speedup 1.0000x reference)
#include <cuda_runtime.h>

#define Hh 512
#define Ww 512
#define Bb 8
#define HW (Hh*Ww)

#define TH 16
#define TW 64
#define CHUNK 4
#define Y1H (TH+2)   // 18
#define Y1W (TW+2)   // 66
#define XH  (TH+4)   // 20
#define XW  72       // padded (68 needed) so conv1 strips never read OOB
#define WP  20       // padded stride for 18 output channels

// One fused kernel: conv1(3->64,3x3,p1)+ReLU -> conv2(64->18,3x3,p1) offsets
// -> deformable conv(3->3,3x3,p1, bilinear). No device scratch.
__global__ __launch_bounds__(256)
void fused_deform_kernel(const float* __restrict__ x,
                         const float* __restrict__ w1, const float* __restrict__ b1,
                         const float* __restrict__ w2, const float* __restrict__ b2,
                         const float* __restrict__ wd, const float* __restrict__ bd,
                         float* __restrict__ out)
{
    __shared__ float sx[3][XH][XW];            // x halo tile          17.3 KB
    __shared__ float sy1[CHUNK][Y1H][Y1W];     // conv1 chunk          19.0 KB
    __shared__ float sw2[CHUNK * 9 * WP];      // conv2 w chunk (T)     2.9 KB
    __shared__ float sw1[64 * 27];             // conv1 weights         6.9 KB
    __shared__ float sb1[64];
    __shared__ float swd[81];
    __shared__ float sbd[3];

    const int tid = threadIdx.x;
    const int b   = blockIdx.z;
    const int y0  = blockIdx.y * TH;
    const int x0  = blockIdx.x * TW;

    // ---- stage constants ----
    for (int i = tid; i < 64 * 27; i += 256) sw1[i] = w1[i];
    if (tid < 64) sb1[tid] = b1[tid];
    if (tid < 81) swd[tid] = wd[tid];          // [o][c][k] flat
    if (tid < 3)  sbd[tid] = bd[tid];

    // ---- stage x halo (rows y0-2..y0+17, cols x0-2..x0+65, zero padded) ----
    for (int i = tid; i < 3 * XH * XW; i += 256) {
        int c  = i / (XH * XW);
        int rr = (i / XW) % XH;
        int cc = i % XW;
        int gy = y0 - 2 + rr;
        int gx = x0 - 2 + cc;
        float v = 0.f;
        if (gy >= 0 && gy < Hh && gx >= 0 && gx < Ww)
            v = __ldg(&x[(size_t)(b * 3 + c) * HW + gy * Ww + gx]);
        sx[c][rr][cc] = v;
    }

    // ---- per-thread offset accumulators: 4 px x 18 channels ----
    float acc[18][4];
#pragma unroll
    for (int co = 0; co < 18; co++) {
        float bv = __ldg(&b2[co]);
        acc[co][0] = bv; acc[co][1] = bv; acc[co][2] = bv; acc[co][3] = bv;
    }

    const int r     = tid >> 4;        // 0..15 : tile row
    const int cbase = (tid & 15) * 4;  // 0..60 : tile col group

    for (int ch0 = 0; ch0 < 64; ch0 += CHUNK) {
        __syncthreads();  // protect sy1/sw2 reuse (also covers initial staging)

        // stage transposed conv2 weight chunk: [cl][tap][co]
        for (int i = tid; i < 18 * CHUNK * 9; i += 256) {
            int co = i / (CHUNK * 9);
            int rr = i % (CHUNK * 9);        // cl*9 + tap
            sw2[rr * WP + co] = __ldg(&w2[co * 576 + ch0 * 9 + rr]);
        }

        // conv1 (+ReLU, image-masked) for CHUNK channels over halo region.
        // 4-col register strips: 54 LDS / 108 FMA per task.
        for (int task = tid; task < CHUNK * Y1H * 17; task += 256) {
            int cl  = task / (Y1H * 17);
            int rem = task % (Y1H * 17);
            int row = rem / 17;
            int c0  = (rem % 17) * 4;
            const float* wv = &sw1[(ch0 + cl) * 27];
            float bv = sb1[ch0 + cl];
            float a0 = bv, a1 = bv, a2 = bv, a3 = bv;
#pragma unroll
            for (int c = 0; c < 3; c++)
#pragma unroll
                for (int dy = 0; dy < 3; dy++)
#pragma unroll
                    for (int dx = 0; dx < 3; dx++) {
                        float wt = wv[c * 9 + dy * 3 + dx];
                        const float* sp = &sx[c][row + dy][c0 + dx];
                        a0 = fmaf(sp[0], wt, a0);
                        a1 = fmaf(sp[1], wt, a1);
                        a2 = fmaf(sp[2], wt, a2);
                        a3 = fmaf(sp[3], wt, a3);
                    }
            int gy = y0 - 1 + row;
            bool okY = (gy >= 0) && (gy < Hh);
            float res[4] = {a0, a1, a2, a3};
#pragma unroll
            for (int j = 0; j < 4; j++) {
                int col = c0 + j;
                if (col < Y1W) {
                    int gx = x0 - 1 + col;
                    bool ok = okY && (gx >= 0) && (gx < Ww);
                    sy1[cl][row][col] = ok ? fmaxf(res[j], 0.f) : 0.f;
                }
            }
        }
        __syncthreads();

        // conv2 accumulate: 4 cin x 9 taps x 18 co x 4 px
#pragma unroll 1
        for (int cl = 0; cl < CHUNK; cl++) {
            float n[3][6];
#pragma unroll
            for (int r2 = 0; r2 < 3; r2++)
#pragma unroll
                for (int j = 0; j < 6; j++)
                    n[r2][j] = sy1[cl][r + r2][cbase + j];
#pragma unroll
            for (int t = 0; t < 9; t++) {
                const int ky = t / 3, kx = t % 3;
                const float* wp = &sw2[(cl * 9 + t) * WP];
                float w[18];
#pragma unroll
                for (int q = 0; q < 4; q++) {
                    float4 w4 = *(const float4*)(wp + 4 * q);
                    w[4*q] = w4.x; w[4*q+1] = w4.y; w[4*q+2] = w4.z; w[4*q+3] = w4.w;
                }
                float2 w2v = *(const float2*)(wp + 16);
                w[16] = w2v.x; w[17] = w2v.y;
#pragma unroll
                for (int co = 0; co < 18; co++) {
                    acc[co][0] = fmaf(n[ky][kx + 0], w[co], acc[co][0]);
                    acc[co][1] = fmaf(n[ky][kx + 1], w[co], acc[co][1]);
                    acc[co][2] = fmaf(n[ky][kx + 2], w[co], acc[co][2]);
                    acc[co][3] = fmaf(n[ky][kx + 3], w[co], acc[co][3]);
                }
            }
        }
    }

    // ---- deformable conv epilogue: offsets live in acc ----
    const int gy = y0 + r;
    const float* xb = x + (size_t)(b * 3) * HW;
    float o[3][4];
#pragma unroll
    for (int j = 0; j < 4; j++) {
        int gx = x0 + cbase + j;
        float a0 = sbd[0], a1 = sbd[1], a2 = sbd[2];
#pragma unroll
        for (int k = 0; k < 9; k++) {
            float dy = acc[2 * k][j];
            float dx = acc[2 * k + 1][j];
            float ys = (float)(gy + k / 3 - 1) + dy;
            float xs = (float)(gx + k % 3 - 1) + dx;
            float yf = floorf(ys), xf = floorf(xs);
            int iy0 = (int)yf, ix0 = (int)xf;
            float fy = ys - yf, fx = xs - xf;
            float s0 = 0.f, s1 = 0.f, s2 = 0.f;
#pragma unroll
            for (int cy = 0; cy < 2; cy++)
#pragma unroll
                for (int cx = 0; cx < 2; cx++) {
                    int iy = iy0 + cy, ix = ix0 + cx;
                    float wgt = (cy ? fy : 1.f - fy) * (cx ? fx : 1.f - fx);
                    bool ok = (iy >= 0) && (iy < Hh) && (ix >= 0) && (ix < Ww);
                    wgt = ok ? wgt : 0.f;
                    int idx = min(max(iy, 0), Hh - 1) * Ww + min(max(ix, 0), Ww - 1);
                    s0 = fmaf(wgt, __ldg(xb + idx), s0);
                    s1 = fmaf(wgt, __ldg(xb + HW + idx), s1);
                    s2 = fmaf(wgt, __ldg(xb + 2 * HW + idx), s2);
                }
            a0 = fmaf(s0, swd[ 0 + k], fmaf(s1, swd[ 9 + k], fmaf(s2, swd[18 + k], a0)));
            a1 = fmaf(s0, swd[27 + k], fmaf(s1, swd[36 + k], fmaf(s2, swd[45 + k], a1)));
            a2 = fmaf(s0, swd[54 + k], fmaf(s1, swd[63 + k], fmaf(s2, swd[72 + k], a2)));
        }
        o[0][j] = a0; o[1][j] = a1; o[2][j] = a2;
    }
#pragma unroll
    for (int c = 0; c < 3; c++) {
        float4 v;
        v.x = o[c][0]; v.y = o[c][1]; v.z = o[c][2]; v.w = o[c][3];
        *(float4*)&out[(size_t)(b * 3 + c) * HW + (size_t)gy * Ww + x0 + cbase] = v;
    }
}

extern "C" void kernel_launch(void* const* d_in, const int* in_sizes, int n_in,
                              void* d_out, int out_size)
{
    const float* x  = (const float*)d_in[0];
    const float* w1 = (const float*)d_in[1];
    const float* b1 = (const float*)d_in[2];
    const float* w2 = (const float*)d_in[3];
    const float* b2 = (const float*)d_in[4];
    const float* wd = (const float*)d_in[5];
    const float* bd = (const float*)d_in[6];
    float* out = (float*)d_out;

    dim3 grid(Ww / TW, Hh / TH, Bb);   // 8 x 32 x 8 = 2048 blocks
    fused_deform_kernel<<<grid, 256>>>(x, w1, b1, w2, b2, wd, bd, out);
}

// round 3
// speedup vs baseline: 1.3646x; 1.3646x over previous
#include <cuda_runtime.h>

#define Hh 512
#define Ww 512
#define Bb 8
#define HW (Hh*Ww)

#define TH 16
#define TW 64
#define CHUNK 4
#define Y1H (TH+2)   // 18
#define Y1W 66       // real cols needed
#define Y1WP 68      // padded stride (mult of 4 -> 16B aligned rows)
#define XH  (TH+4)   // 20
#define XW  72       // padded halo row
#define WP  20       // padded stride for 18 conv2 output channels

__global__ __launch_bounds__(256)
void fused_deform_kernel(const float* __restrict__ x,
                         const float* __restrict__ w1, const float* __restrict__ b1,
                         const float* __restrict__ w2, const float* __restrict__ b2,
                         const float* __restrict__ wd, const float* __restrict__ bd,
                         float* __restrict__ out)
{
    __shared__ __align__(16) float sx[3][XH][XW];          // 17.3 KB
    __shared__ __align__(16) float sy1[CHUNK][Y1H][Y1WP];  // 19.6 KB
    __shared__ __align__(16) float sw2[CHUNK * 9 * WP];    //  2.9 KB
    __shared__ __align__(16) float sw1[64 * 27];           //  6.9 KB
    __shared__ __align__(16) float4 sw1t[27];              // chunk weights transposed [tap][cl]
    __shared__ float sb1[64];
    __shared__ float swd[81];
    __shared__ float sbd[3];

    const int tid = threadIdx.x;
    const int b   = blockIdx.z;
    const int y0  = blockIdx.y * TH;
    const int x0  = blockIdx.x * TW;

    // ---- stage constants ----
    for (int i = tid; i < 64 * 27; i += 256) sw1[i] = __ldg(&w1[i]);
    if (tid < 64) sb1[tid] = __ldg(&b1[tid]);
    if (tid < 81) swd[tid] = __ldg(&wd[tid]);
    if (tid < 3)  sbd[tid] = __ldg(&bd[tid]);

    // ---- stage x halo (rows y0-2..y0+17, cols x0-2..x0+65, zero padded) ----
    for (int i = tid; i < 3 * XH * XW; i += 256) {
        int c  = i / (XH * XW);
        int rr = (i / XW) % XH;
        int cc = i % XW;
        int gy = y0 - 2 + rr;
        int gx = x0 - 2 + cc;
        float v = 0.f;
        if (gy >= 0 && gy < Hh && gx >= 0 && gx < Ww)
            v = __ldg(&x[(size_t)(b * 3 + c) * HW + gy * Ww + gx]);
        sx[c][rr][cc] = v;
    }

    // ---- per-thread offset accumulators: 4 px x 18 channels ----
    float acc[18][4];
#pragma unroll
    for (int co = 0; co < 18; co++) {
        float bv = __ldg(&b2[co]);
        acc[co][0] = bv; acc[co][1] = bv; acc[co][2] = bv; acc[co][3] = bv;
    }

    const int r     = tid >> 4;        // 0..15 : tile row
    const int cbase = (tid & 15) * 4;  // 0..60 : tile col group

    for (int ch0 = 0; ch0 < 64; ch0 += CHUNK) {
        __syncthreads();  // sy1/sw2/sw1t of previous chunk no longer in use

        // stage transposed conv2 weight chunk: [cl][tap][co]
        for (int i = tid; i < 18 * CHUNK * 9; i += 256) {
            int co = i / (CHUNK * 9);
            int rr = i % (CHUNK * 9);        // cl*9 + tap
            sw2[rr * WP + co] = __ldg(&w2[co * 576 + ch0 * 9 + rr]);
        }
        // stage transposed conv1 chunk weights: sw1t[tap] = {cl0,cl1,cl2,cl3}
        if (tid < 108) {
            int t  = tid >> 2;
            int cl = tid & 3;
            ((float*)sw1t)[t * 4 + cl] = sw1[(ch0 + cl) * 27 + t];
        }
        __syncthreads();

        // conv1 (+ReLU, image-masked): one task = 4 channels x 4 px.
        // 18 vec input LDS + 27 LDS.128 weights per 432 FMA.
        for (int task = tid; task < Y1H * 17; task += 256) {
            int row = task / 17;
            int c0  = (task % 17) * 4;

            float v[3][3][6];
#pragma unroll
            for (int c = 0; c < 3; c++)
#pragma unroll
                for (int dy = 0; dy < 3; dy++) {
                    float4 p4 = *(const float4*)&sx[c][row + dy][c0];
                    float2 p2 = *(const float2*)&sx[c][row + dy][c0 + 4];
                    v[c][dy][0] = p4.x; v[c][dy][1] = p4.y;
                    v[c][dy][2] = p4.z; v[c][dy][3] = p4.w;
                    v[c][dy][4] = p2.x; v[c][dy][5] = p2.y;
                }

            float a[4][4];
#pragma unroll
            for (int cl = 0; cl < 4; cl++) {
                float bv = sb1[ch0 + cl];
                a[cl][0] = bv; a[cl][1] = bv; a[cl][2] = bv; a[cl][3] = bv;
            }
#pragma unroll
            for (int t = 0; t < 27; t++) {
                const int c = t / 9, dy = (t / 3) % 3, dx = t % 3;
                float4 w4 = sw1t[t];
#pragma unroll
                for (int j = 0; j < 4; j++) {
                    float vv = v[c][dy][dx + j];
                    a[0][j] = fmaf(vv, w4.x, a[0][j]);
                    a[1][j] = fmaf(vv, w4.y, a[1][j]);
                    a[2][j] = fmaf(vv, w4.z, a[2][j]);
                    a[3][j] = fmaf(vv, w4.w, a[3][j]);
                }
            }

            int gyy = y0 - 1 + row;
            bool okY = (gyy >= 0) && (gyy < Hh);
            bool okJ[4];
#pragma unroll
            for (int j = 0; j < 4; j++) {
                int col = c0 + j;
                int gx  = x0 - 1 + col;
                okJ[j] = okY && (col < Y1W) && (gx >= 0) && (gx < Ww);
            }
#pragma unroll
            for (int cl = 0; cl < 4; cl++) {
                float4 rv;
                rv.x = okJ[0] ? fmaxf(a[cl][0], 0.f) : 0.f;
                rv.y = okJ[1] ? fmaxf(a[cl][1], 0.f) : 0.f;
                rv.z = okJ[2] ? fmaxf(a[cl][2], 0.f) : 0.f;
                rv.w = okJ[3] ? fmaxf(a[cl][3], 0.f) : 0.f;
                *(float4*)&sy1[cl][row][c0] = rv;
            }
        }
        __syncthreads();

        // conv2 accumulate: 4 cin x 9 taps x 18 co x 4 px
#pragma unroll 1
        for (int cl = 0; cl < CHUNK; cl++) {
            float n[3][6];
#pragma unroll
            for (int r2 = 0; r2 < 3; r2++) {
                float4 p4 = *(const float4*)&sy1[cl][r + r2][cbase];
                float2 p2 = *(const float2*)&sy1[cl][r + r2][cbase + 4];
                n[r2][0] = p4.x; n[r2][1] = p4.y; n[r2][2] = p4.z;
                n[r2][3] = p4.w; n[r2][4] = p2.x; n[r2][5] = p2.y;
            }
#pragma unroll
            for (int t = 0; t < 9; t++) {
                const int ky = t / 3, kx = t % 3;
                const float* wp = &sw2[(cl * 9 + t) * WP];
                float w[18];
#pragma unroll
                for (int q = 0; q < 4; q++) {
                    float4 w4 = *(const float4*)(wp + 4 * q);
                    w[4*q] = w4.x; w[4*q+1] = w4.y; w[4*q+2] = w4.z; w[4*q+3] = w4.w;
                }
                float2 w2v = *(const float2*)(wp + 16);
                w[16] = w2v.x; w[17] = w2v.y;
#pragma unroll
                for (int co = 0; co < 18; co++) {
                    acc[co][0] = fmaf(n[ky][kx + 0], w[co], acc[co][0]);
                    acc[co][1] = fmaf(n[ky][kx + 1], w[co], acc[co][1]);
                    acc[co][2] = fmaf(n[ky][kx + 2], w[co], acc[co][2]);
                    acc[co][3] = fmaf(n[ky][kx + 3], w[co], acc[co][3]);
                }
            }
        }
    }

    // ---- deformable conv epilogue: offsets live in acc ----
    const int gy = y0 + r;
    const float* xb = x + (size_t)(b * 3) * HW;
    float o[3][4];
#pragma unroll
    for (int j = 0; j < 4; j++) {
        int gx = x0 + cbase + j;
        float a0 = sbd[0], a1 = sbd[1], a2 = sbd[2];
#pragma unroll
        for (int k = 0; k < 9; k++) {
            float dy = acc[2 * k][j];
            float dx = acc[2 * k + 1][j];
            float ys = (float)(gy + k / 3 - 1) + dy;
            float xs = (float)(gx + k % 3 - 1) + dx;
            float yf = floorf(ys), xf = floorf(xs);
            int iy0 = (int)yf, ix0 = (int)xf;
            float fy = ys - yf, fx = xs - xf;
            float s0 = 0.f, s1 = 0.f, s2 = 0.f;
#pragma unroll
            for (int cy = 0; cy < 2; cy++)
#pragma unroll
                for (int cx = 0; cx < 2; cx++) {
                    int iy = iy0 + cy, ix = ix0 + cx;
                    float wgt = (cy ? fy : 1.f - fy) * (cx ? fx : 1.f - fx);
                    bool ok = (iy >= 0) && (iy < Hh) && (ix >= 0) && (ix < Ww);
                    wgt = ok ? wgt : 0.f;
                    int idx = min(max(iy, 0), Hh - 1) * Ww + min(max(ix, 0), Ww - 1);
                    s0 = fmaf(wgt, __ldg(xb + idx), s0);
                    s1 = fmaf(wgt, __ldg(xb + HW + idx), s1);
                    s2 = fmaf(wgt, __ldg(xb + 2 * HW + idx), s2);
                }
            a0 = fmaf(s0, swd[ 0 + k], fmaf(s1, swd[ 9 + k], fmaf(s2, swd[18 + k], a0)));
            a1 = fmaf(s0, swd[27 + k], fmaf(s1, swd[36 + k], fmaf(s2, swd[45 + k], a1)));
            a2 = fmaf(s0, swd[54 + k], fmaf(s1, swd[63 + k], fmaf(s2, swd[72 + k], a2)));
        }
        o[0][j] = a0; o[1][j] = a1; o[2][j] = a2;
    }
#pragma unroll
    for (int c = 0; c < 3; c++) {
        float4 v;
        v.x = o[c][0]; v.y = o[c][1]; v.z = o[c][2]; v.w = o[c][3];
        *(float4*)&out[(size_t)(b * 3 + c) * HW + (size_t)gy * Ww + x0 + cbase] = v;
    }
}

extern "C" void kernel_launch(void* const* d_in, const int* in_sizes, int n_in,
                              void* d_out, int out_size)
{
    const float* x  = (const float*)d_in[0];
    const float* w1 = (const float*)d_in[1];
    const float* b1 = (const float*)d_in[2];
    const float* w2 = (const float*)d_in[3];
    const float* b2 = (const float*)d_in[4];
    const float* wd = (const float*)d_in[5];
    const float* bd = (const float*)d_in[6];
    float* out = (float*)d_out;

    dim3 grid(Ww / TW, Hh / TH, Bb);   // 8 x 32 x 8 = 2048 blocks
    fused_deform_kernel<<<grid, 256>>>(x, w1, b1, w2, b2, wd, bd, out);
}